// round 5
// baseline (speedup 1.0000x reference)
#include <cuda_runtime.h>
#include <cstdint>

// Problem constants
#define BATCH 16
#define HDIM  1024
#define WDIM  1024
#define HW    (HDIM * WDIM)
#define NPIX  ((long long)BATCH * HW)

// Tile config
#define TX 128
#define TY 64
#define HALO 5
#define PITCH 144                    // (TX + 2*HALO)=138 padded to mult of 16
#define TROWS (TY + 2*HALO)          // 74

// Global accumulators: A0, B0, A1, B1, E  (zero-initialized at load; finalize re-zeroes)
__device__ double g_acc[5];

__device__ __forceinline__ unsigned dp4a_u(unsigned a, unsigned b, unsigned c) {
    return __dp4a(a, b, c);
}

#define ONES 0x01010101u

__global__ __launch_bounds__(256, 4)
void fused_loss_kernel(const float* __restrict__ s0,
                       const float* __restrict__ s1,
                       const int*   __restrict__ tgt) {
    __shared__ __align__(16) unsigned char s_t[TROWS * PITCH];  // target tile + halo (u8)
    __shared__ __align__(4)  unsigned char s_h[TROWS * TX];     // horizontal 11-sums (u8, <=11)
    __shared__ float wred[8][5];

    const int tid = threadIdx.x;
    const int bx = blockIdx.x, by = blockIdx.y, b = blockIdx.z;
    const int gx0 = bx * TX - HALO;
    const int gy0 = by * TY - HALO;

    // ---- Phase 1: load target tile (with zero-padded halo) into u8 smem ----
    const int* tb = tgt + (size_t)b * HW;
    for (int i = tid; i < TROWS * PITCH; i += 256) {
        const int r = i / PITCH;
        const int c = i - r * PITCH;
        int v = 0;
        const int gy = gy0 + r;
        const int gx = gx0 + c;
        if (c < TX + 2*HALO && (unsigned)gy < HDIM && (unsigned)gx < WDIM)
            v = __ldg(tb + gy * WDIM + gx);
        s_t[i] = (unsigned char)v;
    }
    __syncthreads();

    // ---- Phase 2: horizontal 11-sums, 4 outputs/thread-iter via masked dp4a ----
    // base = r*PITCH + 4*g is 4-aligned (PITCH%4==0). Window for output k: bytes [4g+k, 4g+k+10].
    for (int i = tid; i < TROWS * 32; i += 256) {
        const int r = i >> 5;
        const int g = i & 31;
        const unsigned char* row = s_t + r * PITCH + g * 4;
        const unsigned w0 = *(const unsigned*)(row);
        const unsigned w1 = *(const unsigned*)(row + 4);
        const unsigned w2 = *(const unsigned*)(row + 8);
        const unsigned w3 = *(const unsigned*)(row + 12);
        const unsigned o0 = dp4a_u(w0, ONES,        dp4a_u(w1, ONES, dp4a_u(w2, 0x00010101u, 0u)));
        const unsigned o1 = dp4a_u(w0, 0x01010100u, dp4a_u(w1, ONES, dp4a_u(w2, ONES, 0u)));
        const unsigned o2 = dp4a_u(w0, 0x01010000u, dp4a_u(w1, ONES, dp4a_u(w2, ONES, dp4a_u(w3, 0x00000001u, 0u))));
        const unsigned o3 = dp4a_u(w0, 0x01000000u, dp4a_u(w1, ONES, dp4a_u(w2, ONES, dp4a_u(w3, 0x00000101u, 0u))));
        *(unsigned*)(s_h + r * TX + g * 4) = o0 | (o1 << 8) | (o2 << 16) | (o3 << 24);
    }
    __syncthreads();

    // ---- Phase 3: packed vertical sliding 11-sum + fused loss, 4 px/thread ----
    const int xg = tid & 31;           // 32 thread-columns of 4 px
    const int yg = tid >> 5;           // 8 row-groups of 8 rows
    const int x4 = xg * 4;
    const int y0 = yg * 8;

    unsigned box = 0;                  // 4 packed column box-sums (each <= 121)
    #pragma unroll
    for (int r = 0; r < 11; r++)
        box = __vadd4(box, *(const unsigned*)(s_h + (y0 + r) * TX + x4));

    const int gx = bx * TX + x4;
    const size_t rowBase = (size_t)(by * TY) * WDIM + gx;
    const float* p00 = s0 + (size_t)(2 * b) * HW + rowBase;
    const float* p01 = p00 + HW;
    const float* p10 = s1 + (size_t)(2 * b) * HW + rowBase;
    const float* p11 = p10 + HW;

    float A0 = 0.f, B0 = 0.f, A1 = 0.f, B1 = 0.f;
    int E = 0;

    #pragma unroll
    for (int j = 0; j < 8; j++) {
        const int y = y0 + j;
        if (j) {
            box = __vadd4(box, *(const unsigned*)(s_h + (y + 10) * TX + x4));
            box = __vsub4(box, *(const unsigned*)(s_h + (y - 1) * TX + x4));
        }
        // 4 packed center targets (offset is 1 mod 4 -> funnel shift of two aligned words)
        const int off = (y + HALO) * PITCH + x4 + 5;
        const unsigned lo = *(const unsigned*)(s_t + off - 1);
        const unsigned hi = *(const unsigned*)(s_t + off + 3);
        const unsigned t4 = __funnelshift_r(lo, hi, 8);      // bytes: t[x4..x4+3], each 0/1
        const unsigned eq = __vcmpeq4(box, t4 * 121u);       // 0xFF per non-edge byte

        const size_t offr = (size_t)y * WDIM;
        const float4 va0 = *(const float4*)(p00 + offr);
        const float4 vc0 = *(const float4*)(p01 + offr);
        const float4 va1 = *(const float4*)(p10 + offr);
        const float4 vc1 = *(const float4*)(p11 + offr);
        const float a0x[4] = {va0.x, va0.y, va0.z, va0.w};
        const float c0x[4] = {vc0.x, vc0.y, vc0.z, vc0.w};
        const float a1x[4] = {va1.x, va1.y, va1.z, va1.w};
        const float c1x[4] = {vc1.x, vc1.y, vc1.z, vc1.w};

        #pragma unroll
        for (int k = 0; k < 4; k++) {
            const bool t    = (t4 >> (8 * k)) & 1u;
            const bool edge = !((eq >> (8 * k)) & 1u);

            const float a0 = a0x[k], c0 = c0x[k];
            const float a1 = a1x[k], c1 = c1x[k];

            // log-softmax for C=2: lse = max + log(1 + exp(-|d|))
            const float lse0 = fmaxf(a0, c0) + __logf(1.0f + __expf(-fabsf(a0 - c0)));
            const float lpa0 = a0 - lse0, lpb0 = c0 - lse0;
            const float lpt0 = t ? lpb0 : lpa0;

            const float lse1 = fmaxf(a1, c1) + __logf(1.0f + __expf(-fabsf(a1 - c1)));
            const float lpa1 = a1 - lse1, lpb1 = c1 - lse1;
            const float lpt1 = t ? lpb1 : lpa1;

            A0 += lpt0;
            A1 += lpt1;
            if (edge) {
                B0 += (lpa0 + lpb0) - 1.5f * lpt0;
                B1 += (lpa1 + lpb1) - 1.5f * lpt1;
                E++;
            }
        }
    }

    // ---- Block reduction -> 5 double atomics ----
    float vals[5] = {A0, B0, A1, B1, (float)E};
    #pragma unroll
    for (int k = 0; k < 5; k++) {
        #pragma unroll
        for (int off = 16; off; off >>= 1)
            vals[k] += __shfl_down_sync(0xFFFFFFFFu, vals[k], off);
    }
    const int warp = tid >> 5, lane = tid & 31;
    if (lane == 0) {
        #pragma unroll
        for (int k = 0; k < 5; k++) wred[warp][k] = vals[k];
    }
    __syncthreads();
    if (tid == 0) {
        double acc[5] = {0, 0, 0, 0, 0};
        #pragma unroll
        for (int w = 0; w < 8; w++)
            #pragma unroll
            for (int k = 0; k < 5; k++) acc[k] += (double)wred[w][k];
        #pragma unroll
        for (int k = 0; k < 5; k++) atomicAdd(&g_acc[k], acc[k]);
    }
}

// Reads accumulators, writes loss, then re-zeroes accumulators so the next
// (graph-replayed) launch starts clean. Deterministic: same input -> same result.
__global__ void finalize_kernel(float* __restrict__ out) {
    const double N = (double)NPIX;
    const double E = g_acc[4];
    double alpha = E / N;
    if (alpha > 0.2) alpha = 0.2;
    const double l0 = -(g_acc[0] + alpha * g_acc[1]) / N;
    const double l1 = -(g_acc[2] + alpha * g_acc[3]) / N;
    out[0] = (float)(l0 + 0.5 * l1);
    #pragma unroll
    for (int k = 0; k < 5; k++) g_acc[k] = 0.0;
}

extern "C" void kernel_launch(void* const* d_in, const int* in_sizes, int n_in,
                              void* d_out, int out_size) {
    const float* s0 = (const float*)d_in[0];
    const float* s1 = (const float*)d_in[1];
    const int*   tg = (const int*)d_in[2];

    dim3 grid(WDIM / TX, HDIM / TY, BATCH);   // (8, 16, 16) = 2048 blocks
    fused_loss_kernel<<<grid, 256>>>(s0, s1, tg);
    finalize_kernel<<<1, 1>>>((float*)d_out);
}